// round 6
// baseline (speedup 1.0000x reference)
#include <cuda_runtime.h>
#include <cstdint>

// CRF loss: mean_b( logZ_b - gold_b );  B=256, T=1024, C=64
// Scaled-domain forward: p_{t+1} = (E^T p_t) ∘ W_t / c_t,  logZ += log c_t.
// 128-thread blocks = 2 independent 64-thread batch groups (fills all 4 SMSPs,
// 1 warp/SMSP at grid=128 on 148 SMs). Matvec uses packed fma.rn.f32x2.

#define BD 256
#define TD 1024
#define CD 64
#define LOG2E 1.4426950408889634f
#define LN2   0.6931471805599453f

__device__ float g_partial[BD];

__device__ __forceinline__ float fast_exp2(float x) {
    float y; asm("ex2.approx.ftz.f32 %0, %1;" : "=f"(y) : "f"(x)); return y;
}
__device__ __forceinline__ float fast_log2(float x) {
    float y; asm("lg2.approx.ftz.f32 %0, %1;" : "=f"(y) : "f"(x)); return y;
}
__device__ __forceinline__ float fast_rcp(float x) {
    float y; asm("rcp.approx.ftz.f32 %0, %1;" : "=f"(y) : "f"(x)); return y;
}
__device__ __forceinline__ unsigned long long pack2(float lo, float hi) {
    unsigned long long r;
    asm("mov.b64 %0, {%1, %2};" : "=l"(r) : "f"(lo), "f"(hi)); return r;
}
__device__ __forceinline__ unsigned long long ffma2(unsigned long long a,
                                                    unsigned long long b,
                                                    unsigned long long c) {
    unsigned long long d;
    asm("fma.rn.f32x2 %0, %1, %2, %3;" : "=l"(d) : "l"(a), "l"(b), "l"(c));
    return d;
}
__device__ __forceinline__ float2 unpack2(unsigned long long v) {
    float2 f;
    asm("mov.b64 {%0, %1}, %2;" : "=f"(f.x), "=f"(f.y) : "l"(v)); return f;
}

// per-group barrier (64 threads = 2 warps), ids 1 and 2
#define GBAR(g) asm volatile("bar.sync %0, 64;" :: "r"((g) + 1) : "memory")

__global__ __launch_bounds__(128)
void crf_forward_kernel(const float* __restrict__ emissions,
                        const float* __restrict__ transitions,
                        const float* __restrict__ start_t,
                        const float* __restrict__ end_t,
                        const int*   __restrict__ tags,
                        const float* __restrict__ mask)
{
    __shared__ __align__(16) float psh[2][2][CD];  // [group][buf][tag]
    __shared__ float swp[2][2];
    __shared__ float gred[2][2];
    __shared__ int   cred[2][2];

    const int g    = threadIdx.x >> 6;        // batch group 0/1
    const int j    = threadIdx.x & 63;        // tag owned by this thread
    const int w    = (threadIdx.x >> 5) & 1;  // warp within group
    const int lane = threadIdx.x & 31;
    const int b    = blockIdx.x * 2 + g;

    const float* em = emissions + (size_t)b * TD * CD;
    const int*   tg = tags      + (size_t)b * TD;
    const float* mk = mask      + (size_t)b * TD;

    // ---- E column j, packed in pairs: Ecp[k] = {E[2k][j], E[2k+1][j]} ----
    unsigned long long Ecp[CD / 2];
    #pragma unroll
    for (int k = 0; k < CD / 2; k++) {
        float e0 = fast_exp2(transitions[(2 * k)     * CD + j] * LOG2E);
        float e1 = fast_exp2(transitions[(2 * k + 1) * CD + j] * LOG2E);
        Ecp[k] = pack2(e0, e1);
    }

    // ---- gold score (parallel over t within the group) ----
    float gp  = 0.f;
    int   cnt = 0;
    for (int t = j; t < TD; t += CD) {
        float m = mk[t];
        cnt += (int)m;
        if (t >= 1) {
            int tc = tg[t], tp = tg[t - 1];
            gp += m * (em[t * CD + tc] + transitions[tp * CD + tc]);
        }
    }
    #pragma unroll
    for (int off = 16; off; off >>= 1) {
        gp  += __shfl_xor_sync(0xffffffffu, gp,  off);
        cnt += __shfl_xor_sync(0xffffffffu, cnt, off);
    }
    if (lane == 0) { gred[g][w] = gp; cred[g][w] = cnt; }

    // ---- forward init (t = 0), linear domain ----
    float myp = fast_exp2((start_t[j] + em[j]) * LOG2E);
    psh[g][0][j] = myp;

    // ---- prefetch ring: W = exp(emit), mask — 4 deep ----
    float Wr[4], mr[4];
    #pragma unroll
    for (int t0 = 1; t0 <= 4; t0++) {
        Wr[t0 & 3] = fast_exp2(em[t0 * CD + j] * LOG2E);
        mr[t0 & 3] = mk[t0];
    }

    GBAR(g);   // psh[g][0], gred/cred visible within group

    float gold = 0.f;
    if (j == 0) {
        int seqlen  = cred[g][0] + cred[g][1];
        int lastidx = seqlen - 1; if (lastidx < 0) lastidx = 0;
        int t0 = tg[0], tl = tg[lastidx];
        gold = gred[g][0] + gred[g][1] + start_t[t0] + em[t0] + end_t[tl];
    }

    // ---- forward recursion: one named barrier per step ----
    float logAcc = 0.f;
    int   cur    = 0;

    #pragma unroll 4
    for (int t = 1; t < TD; t++) {
        const int   slot = t & 3;
        const float W    = Wr[slot];
        const float mt   = mr[slot];

        const int tp = t + 4;                    // refill ring (off-chain)
        if (tp < TD) {
            Wr[slot] = fast_exp2(em[tp * CD + j] * LOG2E);
            mr[slot] = mk[tp];
        }

        const float* pc = psh[g][cur];
        const float  c  = pc[0];                 // broadcast LDS (normalizer)
        const float  r  = fast_rcp(c);
        logAcc += fast_log2(c);

        unsigned long long a0 = 0ull, a1 = 0ull, a2 = 0ull, a3 = 0ull;
        #pragma unroll
        for (int i = 0; i < CD; i += 8) {
            ulonglong2 qa = *(const ulonglong2*)&pc[i];      // p[i..i+3]
            ulonglong2 qb = *(const ulonglong2*)&pc[i + 4];  // p[i+4..i+7]
            a0 = ffma2(qa.x, Ecp[i / 2 + 0], a0);
            a1 = ffma2(qa.y, Ecp[i / 2 + 1], a1);
            a2 = ffma2(qb.x, Ecp[i / 2 + 2], a2);
            a3 = ffma2(qb.y, Ecp[i / 2 + 3], a3);
        }
        float2 f0 = unpack2(a0), f1 = unpack2(a1);
        float2 f2 = unpack2(a2), f3 = unpack2(a3);
        const float s  = ((f0.x + f0.y) + (f1.x + f1.y))
                       + ((f2.x + f2.y) + (f3.x + f3.y));
        const float pn = s * W * r;
        // masked step: p scaled by r (cancels logAcc += log2 c)
        myp = (mt > 0.f) ? pn : myp * r;
        psh[g][cur ^ 1][j] = myp;
        GBAR(g);
        cur ^= 1;
    }

    // ---- final: logZ = LN2 * (logAcc + log2(sum_j p_j * exp(end_j))) ----
    float v = myp * fast_exp2(end_t[j] * LOG2E);
    #pragma unroll
    for (int off = 16; off; off >>= 1)
        v += __shfl_xor_sync(0xffffffffu, v, off);
    if (lane == 0) swp[g][w] = v;
    GBAR(g);

    if (j == 0) {
        float fwd = (logAcc + fast_log2(swp[g][0] + swp[g][1])) * LN2;
        g_partial[b] = fwd - gold;
    }
}

__global__ void crf_reduce_kernel(float* __restrict__ out)
{
    const int j = threadIdx.x;     // 256 threads
    float v = g_partial[j];
    __shared__ float sm[8];
    #pragma unroll
    for (int off = 16; off; off >>= 1)
        v += __shfl_xor_sync(0xffffffffu, v, off);
    if ((j & 31) == 0) sm[j >> 5] = v;
    __syncthreads();
    if (j < 8) {
        v = sm[j];
        #pragma unroll
        for (int off = 4; off; off >>= 1)
            v += __shfl_xor_sync(0x000000ffu, v, off);
        if (j == 0) out[0] = v * (1.0f / BD);
    }
}

extern "C" void kernel_launch(void* const* d_in, const int* in_sizes, int n_in,
                              void* d_out, int out_size)
{
    const float* emissions   = (const float*)d_in[0];
    const float* transitions = (const float*)d_in[1];
    const float* start_t     = (const float*)d_in[2];
    const float* end_t       = (const float*)d_in[3];
    const int*   tags        = (const int*)  d_in[4];
    const float* mask        = (const float*)d_in[5];
    float* out = (float*)d_out;

    crf_forward_kernel<<<BD / 2, 128>>>(emissions, transitions, start_t, end_t, tags, mask);
    crf_reduce_kernel<<<1, BD>>>(out);
}